// round 12
// baseline (speedup 1.0000x reference)
#include <cuda_runtime.h>
#include <cstdint>

#define NEG_CLAMP -20.0f
#define EPSV 1e-6f

static constexpr int Ll = 4096, Hh = 16, Ee = 64;
static constexpr int BH = 128;             // B*H
static constexpr int RS = Hh * Ee;         // 1024 floats per L-row
static constexpr int SPLIT = 8;
static constexpr int ROWS1 = Ll / SPLIT;   // 512
static constexpr int TILE = 64;            // pass-1 window rows
static constexpr int NT1 = ROWS1 / TILE;   // 8
static constexpr int CH2 = 1024;           // pass-2 rows per block
static constexpr int T2 = 128;             // pass-2 window rows
static constexpr int NT2 = CH2 / T2;       // 8

__device__ float g_kv_part[SPLIT * BH * Ee * Ee];
__device__ float g_ks_part[SPLIT * BH * Ee];
__device__ float g_kv[BH * Ee * Ee];
__device__ float g_ks[BH * Ee];

typedef unsigned long long u64;

__device__ __forceinline__ u64 pack2(float x, float y) {
    u64 r; asm("mov.b64 %0, {%1, %2};" : "=l"(r) : "f"(x), "f"(y)); return r;
}
__device__ __forceinline__ float2 unpack2(u64 v) {
    float2 r; asm("mov.b64 {%0, %1}, %2;" : "=f"(r.x), "=f"(r.y) : "l"(v)); return r;
}
__device__ __forceinline__ u64 ffma2(u64 a, u64 b, u64 c) {
    u64 d; asm("fma.rn.f32x2 %0, %1, %2, %3;" : "=l"(d) : "l"(a), "l"(b), "l"(c)); return d;
}
__device__ __forceinline__ u64 fmul2(u64 a, u64 b) {
    u64 d; asm("mul.rn.f32x2 %0, %1, %2;" : "=l"(d) : "l"(a), "l"(b)); return d;
}
__device__ __forceinline__ void cpa16(uint32_t dst, const float* src) {
    asm volatile("cp.async.cg.shared.global [%0], [%1], 16;" :: "r"(dst), "l"(src));
}
#define CP_COMMIT() asm volatile("cp.async.commit_group;")
#define CP_WAIT1()  asm volatile("cp.async.wait_group 1;")

// named producer/consumer barriers (id 0 reserved for __syncthreads)
#define BAR_SYNC(id)   asm volatile("bar.sync %0, 256;"   :: "r"(id) : "memory")
#define BAR_ARRIVE(id) asm volatile("bar.arrive %0, 256;" :: "r"(id) : "memory")
// consumer-only barrier (128 threads): orders consumers among themselves
#define BAR_CONS()     asm volatile("bar.sync 5, 128;" ::: "memory")
#define FULLB(s)  (1 + (s))
#define EMPTYB(s) (3 + (s))

// 64-float rows (16 chunks): chunk k -> slot (k>>1) + (k&1)*8 (bijection).
// Reader thread dg wants chunks {2dg,2dg+1} -> floats {4dg, 32+4dg}.
__device__ __forceinline__ int pvslot(int k) { return (k >> 1) + ((k & 1) << 3); }

// Dup-pair row layout (stride 132 floats). Pair c = 8p+i at float
// 32*(i>>1) + 4p + 2*(i&1). Reader LDS.128 at 32j + 4g -> pairs (8g+2j, +1).

// ---------------------------------------------------------------------------
// Pass 1: KV_partial = phi(K)^T V per (head, L-split) + ksum_partial.
// Warps 0-3: softmax producers. Warps 4-7: GEMM consumers, 8e x 8d per thread,
// contraction split: warp-pair (4,5) rows 0-31, (6,7) rows 32-63 per window.
// smem floats: v[2][4096]=8192 | phi[2][64*132]=16896 | kst[1024] = 26112
// ---------------------------------------------------------------------------
__global__ void __launch_bounds__(256, 2) k_pass1(const float* __restrict__ Kin,
                                                  const float* __restrict__ Vin,
                                                  const float* __restrict__ D1) {
    extern __shared__ __align__(16) float sm1[];
    float* s_v   = sm1;             // 2 x 4096 (pvslot-permuted)
    float* s_phi = sm1 + 8192;      // 2 x 8448 (dup pairs, stride 132)
    float* s_kst = sm1 + 25088;     // 16 x 64
    const uint32_t sb = (uint32_t)__cvta_generic_to_shared(sm1);

    const int bh = blockIdx.x / SPLIT, sp = blockIdx.x % SPLIT;
    const int b = bh >> 4, h = bh & 15;
    const int tid = threadIdx.x, w = tid >> 5, lane = tid & 31;
    const float invT = 1.0f / log1pf(__expf(*D1));
    const float* Kb = Kin + (long)b * Ll * RS + h * Ee + (long)sp * ROWS1 * RS;
    const float* Vb = Vin + (long)b * Ll * RS + h * Ee + (long)sp * ROWS1 * RS;

    if (w < 4) {
        // ================= producers =================
        const int sub = lane >> 3, p = lane & 7;    // 8 lanes per row
        float ksl[8];
        #pragma unroll
        for (int i = 0; i < 8; i++) ksl[i] = 0.f;

        for (int t = 0; t < NT1; t++) {
            if (t >= 2) BAR_SYNC(EMPTYB(t & 1));
            float* phib = s_phi + (t & 1) * 8448;
            const float* ksrc = Kb + (long)t * TILE * RS;
            float4 RA[4], RB[4];
            #pragma unroll
            for (int it = 0; it < 4; it++) {
                const float* kp = ksrc + (long)(w * 16 + it * 4 + sub) * RS + 8 * p;
                RA[it] = *(const float4*)kp;
                RB[it] = *(const float4*)(kp + 4);
            }
            #pragma unroll
            for (int it = 0; it < 4; it++) {
                const int r = w * 16 + it * 4 + sub;
                float e0 = __expf((RA[it].x < 0.f ? NEG_CLAMP : RA[it].x) * invT);
                float e1 = __expf((RA[it].y < 0.f ? NEG_CLAMP : RA[it].y) * invT);
                float e2 = __expf((RA[it].z < 0.f ? NEG_CLAMP : RA[it].z) * invT);
                float e3 = __expf((RA[it].w < 0.f ? NEG_CLAMP : RA[it].w) * invT);
                float e4 = __expf((RB[it].x < 0.f ? NEG_CLAMP : RB[it].x) * invT);
                float e5 = __expf((RB[it].y < 0.f ? NEG_CLAMP : RB[it].y) * invT);
                float e6 = __expf((RB[it].z < 0.f ? NEG_CLAMP : RB[it].z) * invT);
                float e7 = __expf((RB[it].w < 0.f ? NEG_CLAMP : RB[it].w) * invT);
                float ls = ((e0 + e1) + (e2 + e3)) + ((e4 + e5) + (e6 + e7));
                ls += __shfl_xor_sync(0xffffffffu, ls, 1);
                ls += __shfl_xor_sync(0xffffffffu, ls, 2);
                ls += __shfl_xor_sync(0xffffffffu, ls, 4);
                float rs = 1.0f / ls;
                e0 *= rs; e1 *= rs; e2 *= rs; e3 *= rs;
                e4 *= rs; e5 *= rs; e6 *= rs; e7 *= rs;
                ksl[0] += e0; ksl[1] += e1; ksl[2] += e2; ksl[3] += e3;
                ksl[4] += e4; ksl[5] += e5; ksl[6] += e6; ksl[7] += e7;
                float* pr = phib + r * 132 + 4 * p;
                *(u64*)(pr)      = pack2(e0, e0);
                *(u64*)(pr + 2)  = pack2(e1, e1);
                *(u64*)(pr + 32) = pack2(e2, e2);
                *(u64*)(pr + 34) = pack2(e3, e3);
                *(u64*)(pr + 64) = pack2(e4, e4);
                *(u64*)(pr + 66) = pack2(e5, e5);
                *(u64*)(pr + 96) = pack2(e6, e6);
                *(u64*)(pr + 98) = pack2(e7, e7);
            }
            BAR_ARRIVE(FULLB(t & 1));
        }
        // stage ksum partials
        float* kr = s_kst + (w * 4 + sub) * 64 + 8 * p;
        *(float4*)(kr)     = make_float4(ksl[0], ksl[1], ksl[2], ksl[3]);
        *(float4*)(kr + 4) = make_float4(ksl[4], ksl[5], ksl[6], ksl[7]);
    } else {
        // ================= consumers =================
        const int grp = (tid >> 6) - 2;          // 0: warps 4,5; 1: warps 6,7
        const int cw64 = tid & 63;
        const int eg = cw64 >> 3, dg = cw64 & 7; // e 8eg..+7, d 8dg..+7
        const int cw = tid & 127;                // for copies / BAR_CONS
        u64 acc[8][4];
        #pragma unroll
        for (int i = 0; i < 8; i++)
            #pragma unroll
            for (int j = 0; j < 4; j++) acc[i][j] = 0ull;

        auto issue_copy = [&](int tile) {
            if (tile < NT1) {
                const float* vsrc = Vb + (long)tile * TILE * RS;
                const uint32_t vd = sb + (uint32_t)((tile & 1) * 4096) * 4u;
                #pragma unroll
                for (int c = 0; c < 8; c++) {
                    int lin = cw + 128 * c;
                    int r = lin >> 4, k = lin & 15;
                    cpa16(vd + (uint32_t)(r * 64 + pvslot(k) * 4) * 4u,
                          vsrc + (long)r * RS + k * 4);
                }
            }
            CP_COMMIT();
        };

        issue_copy(0);

        for (int t = 0; t < NT1; t++) {
            BAR_SYNC(FULLB(t & 1));   // phi(t) ready; all consumers past gemm(t-1)
            issue_copy(t + 1);        // slot (t+1)&1 free
            CP_WAIT1();               // OWN copies of v(t) landed
            BAR_CONS();               // ALL consumers' copies of v(t) landed
            const float* vt = s_v + (t & 1) * 4096 + grp * 32 * 64;
            const float* pb = s_phi + (t & 1) * 8448 + grp * 32 * 132;
            #pragma unroll 2
            for (int r = 0; r < 32; r++) {
                const float* pr = pb + r * 132 + 4 * eg;
                ulonglong2 P0 = *(const ulonglong2*)(pr);
                ulonglong2 P1 = *(const ulonglong2*)(pr + 32);
                ulonglong2 P2 = *(const ulonglong2*)(pr + 64);
                ulonglong2 P3 = *(const ulonglong2*)(pr + 96);
                u64 pe[8] = {P0.x, P0.y, P1.x, P1.y, P2.x, P2.y, P3.x, P3.y};
                const float* vr = vt + r * 64;
                ulonglong2 V0 = *(const ulonglong2*)(vr + 4 * dg);        // d 8dg..+3
                ulonglong2 V1 = *(const ulonglong2*)(vr + 32 + 4 * dg);   // d 8dg+4..+7
                u64 vv[4] = {V0.x, V0.y, V1.x, V1.y};
                #pragma unroll
                for (int i = 0; i < 8; i++)
                    #pragma unroll
                    for (int j = 0; j < 4; j++)
                        acc[i][j] = ffma2(pe[i], vv[j], acc[i][j]);
            }
            BAR_ARRIVE(EMPTYB(t & 1));
        }

        // RACE FIX (R10 bug): all consumers must be past gemm(7)'s V reads
        // before anyone overwrites the V ring with contraction partials.
        BAR_CONS();

        // write contraction partials to smem (V slots now provably dead)
        float* part = sm1 + grp * 4096;
        #pragma unroll
        for (int i = 0; i < 8; i++) {
            float2 a0 = unpack2(acc[i][0]), a1 = unpack2(acc[i][1]);
            float2 a2 = unpack2(acc[i][2]), a3 = unpack2(acc[i][3]);
            float* q = part + (8 * eg + i) * 64 + 8 * dg;
            *(float4*)(q)     = make_float4(a0.x, a0.y, a1.x, a1.y);
            *(float4*)(q + 4) = make_float4(a2.x, a2.y, a3.x, a3.y);
        }
    }

    __syncthreads();
    // merge the two contraction halves + store (all 256 threads, deterministic)
    {
        float* dst = g_kv_part + ((long)sp * BH + bh) * 4096;
        #pragma unroll
        for (int c = 0; c < 4; c++) {
            int off = tid * 16 + c * 4;
            float4 a = *(const float4*)(sm1 + off);
            float4 bq = *(const float4*)(sm1 + 4096 + off);
            *(float4*)(dst + off) = make_float4(a.x + bq.x, a.y + bq.y,
                                                a.z + bq.z, a.w + bq.w);
        }
        if (tid < 64) {
            float s = 0.f;
            #pragma unroll
            for (int i = 0; i < 16; i++) s += s_kst[i * 64 + tid];
            g_ks_part[((long)sp * BH + bh) * 64 + tid] = s;
        }
    }
}

// ---------------------------------------------------------------------------
// Deterministic split reduction (512 blocks)
// ---------------------------------------------------------------------------
__global__ void __launch_bounds__(256) k_reduce() {
    const int bh = blockIdx.x >> 2, part = blockIdx.x & 3;
    const int tid = threadIdx.x;
    const int i4 = part * 1024 + tid * 4;
    float4 s = make_float4(0.f, 0.f, 0.f, 0.f);
    #pragma unroll
    for (int sp = 0; sp < SPLIT; sp++) {
        float4 v = *(const float4*)(g_kv_part + ((long)sp * BH + bh) * 4096 + i4);
        s.x += v.x; s.y += v.y; s.z += v.z; s.w += v.w;
    }
    *(float4*)(g_kv + (long)bh * 4096 + i4) = s;
    if (part == 0 && tid < 64) {
        float t = 0.f;
        #pragma unroll
        for (int sp = 0; sp < SPLIT; sp++)
            t += g_ks_part[((long)sp * BH + bh) * 64 + tid];
        g_ks[(long)bh * 64 + tid] = t;
    }
}

// ---------------------------------------------------------------------------
// Pass 2: out_l = (phi(q_l) . KV) * z_l. 512 blocks, one head x 1024 rows.
// Warps 0-3 produce qT (transposed) + z; warps 4-7 GEMM+store (row-pair f32x2).
// smem floats: kvd[64*128]=8192 | qT[2][64*130]=16640 | z[2][128] | ks[64]
// ---------------------------------------------------------------------------
__global__ void __launch_bounds__(256, 2) k_pass2(const float* __restrict__ Qin,
                                                  float* __restrict__ Out,
                                                  const float* __restrict__ D1) {
    extern __shared__ __align__(16) float sm2[];
    float* s_kvd = sm2;              // 8192 (dup pairs, stride 128)
    float* s_qT  = sm2 + 8192;       // 2 x 8320: [e][row], stride 130
    float* s_z   = sm2 + 24832;      // 2 x 128
    float* s_ks  = sm2 + 25088;      // 64

    const int bh = blockIdx.x >> 2, chunk = blockIdx.x & 3;
    const int b = bh >> 4, h = bh & 15;
    const int tid = threadIdx.x, w = tid >> 5, lane = tid & 31;
    const float invT = 1.0f / log1pf(__expf(*D1));
    const float* Qb = Qin + (long)b * Ll * RS + h * Ee + (long)chunk * CH2 * RS;
    float*       Ob = Out + (long)b * Ll * RS + h * Ee + (long)chunk * CH2 * RS;

    // stage KV duplicated + ksum (all threads), then diverge into roles
    {
        const float* kvsrc = g_kv + (long)bh * 4096;
        #pragma unroll
        for (int c = 0; c < 4; c++) {
            int i4 = tid + 256 * c;
            float4 v4 = *(const float4*)(kvsrc + i4 * 4);
            int e = i4 >> 4, d0 = (i4 & 15) * 4;
            float* rowb = s_kvd + e * 128 + 4 * (d0 >> 3);
            const int j2 = (d0 & 7) >> 1;   // 0 or 2
            *(u64*)(rowb + 32 * j2)           = pack2(v4.x, v4.x);
            *(u64*)(rowb + 32 * j2 + 2)       = pack2(v4.y, v4.y);
            *(u64*)(rowb + 32 * (j2 + 1))     = pack2(v4.z, v4.z);
            *(u64*)(rowb + 32 * (j2 + 1) + 2) = pack2(v4.w, v4.w);
        }
        if (tid < 64) s_ks[tid] = g_ks[(long)bh * 64 + tid];
    }
    __syncthreads();

    if (w < 4) {
        // ================= producers =================
        const int sub = lane >> 3, p = lane & 7;
        float myks[8];
        {
            float4 kA = *(const float4*)(s_ks + 8 * p);
            float4 kB = *(const float4*)(s_ks + 8 * p + 4);
            myks[0] = kA.x; myks[1] = kA.y; myks[2] = kA.z; myks[3] = kA.w;
            myks[4] = kB.x; myks[5] = kB.y; myks[6] = kB.z; myks[7] = kB.w;
        }
        for (int t = 0; t < NT2; t++) {
            if (t >= 2) BAR_SYNC(EMPTYB(t & 1));
            float* qb = s_qT + (t & 1) * 8320;
            float* zb = s_z + (t & 1) * 128;
            const float* qsrc = Qb + (long)t * T2 * RS;
            #pragma unroll
            for (int half = 0; half < 2; half++) {
                float4 RA[4], RB[4];
                #pragma unroll
                for (int i2 = 0; i2 < 4; i2++) {
                    const int r = w * 32 + (half * 4 + i2) * 4 + sub;
                    const float* qp = qsrc + (long)r * RS + 8 * p;
                    RA[i2] = *(const float4*)qp;
                    RB[i2] = *(const float4*)(qp + 4);
                }
                #pragma unroll
                for (int i2 = 0; i2 < 4; i2++) {
                    const int r = w * 32 + (half * 4 + i2) * 4 + sub;
                    float e0 = __expf((RA[i2].x < 0.f ? NEG_CLAMP : RA[i2].x) * invT);
                    float e1 = __expf((RA[i2].y < 0.f ? NEG_CLAMP : RA[i2].y) * invT);
                    float e2 = __expf((RA[i2].z < 0.f ? NEG_CLAMP : RA[i2].z) * invT);
                    float e3 = __expf((RA[i2].w < 0.f ? NEG_CLAMP : RA[i2].w) * invT);
                    float e4 = __expf((RB[i2].x < 0.f ? NEG_CLAMP : RB[i2].x) * invT);
                    float e5 = __expf((RB[i2].y < 0.f ? NEG_CLAMP : RB[i2].y) * invT);
                    float e6 = __expf((RB[i2].z < 0.f ? NEG_CLAMP : RB[i2].z) * invT);
                    float e7 = __expf((RB[i2].w < 0.f ? NEG_CLAMP : RB[i2].w) * invT);
                    float ls = ((e0 + e1) + (e2 + e3)) + ((e4 + e5) + (e6 + e7));
                    float dt = ((e0 * myks[0] + e1 * myks[1]) + (e2 * myks[2] + e3 * myks[3]))
                             + ((e4 * myks[4] + e5 * myks[5]) + (e6 * myks[6] + e7 * myks[7]));
                    #pragma unroll
                    for (int o = 1; o <= 4; o <<= 1) {
                        ls += __shfl_xor_sync(0xffffffffu, ls, o);
                        dt += __shfl_xor_sync(0xffffffffu, dt, o);
                    }
                    float rs = 1.0f / ls;
                    float zz = 1.0f / (dt * rs + EPSV);
                    e0 *= rs; e1 *= rs; e2 *= rs; e3 *= rs;
                    e4 *= rs; e5 *= rs; e6 *= rs; e7 *= rs;
                    qb[(8 * p + 0) * 130 + r] = e0;
                    qb[(8 * p + 1) * 130 + r] = e1;
                    qb[(8 * p + 2) * 130 + r] = e2;
                    qb[(8 * p + 3) * 130 + r] = e3;
                    qb[(8 * p + 4) * 130 + r] = e4;
                    qb[(8 * p + 5) * 130 + r] = e5;
                    qb[(8 * p + 6) * 130 + r] = e6;
                    qb[(8 * p + 7) * 130 + r] = e7;
                    if (p == 0) zb[r] = zz;
                }
            }
            BAR_ARRIVE(FULLB(t & 1));
        }
    } else {
        // ================= consumers =================
        const int cw = tid & 127;
        const int rg = cw >> 3, dg = cw & 7;   // rows 8rg..+7, d 8dg..+7
        for (int t = 0; t < NT2; t++) {
            BAR_SYNC(FULLB(t & 1));
            const float* qb = s_qT + (t & 1) * 8320;
            const float* zb = s_z + (t & 1) * 128;
            u64 acc[4][8];
            #pragma unroll
            for (int pr = 0; pr < 4; pr++)
                #pragma unroll
                for (int j = 0; j < 8; j++) acc[pr][j] = 0ull;
            #pragma unroll 2
            for (int e = 0; e < Ee; e++) {
                const float* qc = qb + e * 130 + 8 * rg;
                u64 q0 = *(const u64*)(qc);
                u64 q1 = *(const u64*)(qc + 2);
                u64 q2 = *(const u64*)(qc + 4);
                u64 q3 = *(const u64*)(qc + 6);
                const float* kr = s_kvd + e * 128 + 4 * dg;
                ulonglong2 K0 = *(const ulonglong2*)(kr);
                ulonglong2 K1 = *(const ulonglong2*)(kr + 32);
                ulonglong2 K2 = *(const ulonglong2*)(kr + 64);
                ulonglong2 K3 = *(const ulonglong2*)(kr + 96);
                u64 kd[8] = {K0.x, K0.y, K1.x, K1.y, K2.x, K2.y, K3.x, K3.y};
                #pragma unroll
                for (int j = 0; j < 8; j++) {
                    acc[0][j] = ffma2(q0, kd[j], acc[0][j]);
                    acc[1][j] = ffma2(q1, kd[j], acc[1][j]);
                    acc[2][j] = ffma2(q2, kd[j], acc[2][j]);
                    acc[3][j] = ffma2(q3, kd[j], acc[3][j]);
                }
            }
            #pragma unroll
            for (int pr = 0; pr < 4; pr++) {
                const int r0 = 8 * rg + 2 * pr;
                const u64 zp = pack2(zb[r0], zb[r0 + 1]);
                float2 sc[8];
                #pragma unroll
                for (int j = 0; j < 8; j++) sc[j] = unpack2(fmul2(acc[pr][j], zp));
                float* oA = Ob + (long)(t * T2 + r0) * RS + 8 * dg;
                *(float4*)(oA)     = make_float4(sc[0].x, sc[1].x, sc[2].x, sc[3].x);
                *(float4*)(oA + 4) = make_float4(sc[4].x, sc[5].x, sc[6].x, sc[7].x);
                float* oB = oA + RS;
                *(float4*)(oB)     = make_float4(sc[0].y, sc[1].y, sc[2].y, sc[3].y);
                *(float4*)(oB + 4) = make_float4(sc[4].y, sc[5].y, sc[6].y, sc[7].y);
            }
            BAR_ARRIVE(EMPTYB(t & 1));
        }
    }
}

extern "C" void kernel_launch(void* const* d_in, const int* in_sizes, int n_in,
                              void* d_out, int out_size) {
    const float* Q  = (const float*)d_in[0];
    const float* K  = (const float*)d_in[1];
    const float* V  = (const float*)d_in[2];
    const float* D1 = (const float*)d_in[3];
    float* O = (float*)d_out;

    const int smem1 = 26112 * 4;  // 104448 B
    const int smem2 = 25152 * 4;  // 100608 B
    cudaFuncSetAttribute(k_pass1, cudaFuncAttributeMaxDynamicSharedMemorySize, smem1);
    cudaFuncSetAttribute(k_pass2, cudaFuncAttributeMaxDynamicSharedMemorySize, smem2);

    k_pass1 <<<BH * SPLIT, 256, smem1>>>(K, V, D1);
    k_reduce<<<BH * 4, 256>>>();
    k_pass2 <<<BH * 4, 256, smem2>>>(Q, O, D1);
}

// round 15
// speedup vs baseline: 1.7821x; 1.7821x over previous
#include <cuda_runtime.h>
#include <cstdint>

#define NEG_CLAMP -20.0f
#define EPSV 1e-6f

static constexpr int Ll = 4096, Hh = 16, Ee = 64;
static constexpr int BH = 128;             // B*H
static constexpr int RS = Hh * Ee;         // 1024 floats per L-row
static constexpr int SPLIT = 8;
static constexpr int ROWS1 = Ll / SPLIT;   // 512
static constexpr int TILE = 64;            // pass-1 window rows
static constexpr int NT1 = ROWS1 / TILE;   // 8
static constexpr int CH2 = 512;            // pass-2 rows per block
static constexpr int T2 = 128;             // pass-2 window rows
static constexpr int NT2 = CH2 / T2;       // 4

__device__ float g_kv_part[SPLIT * BH * Ee * Ee];
__device__ float g_ks_part[SPLIT * BH * Ee];
__device__ float g_kv[BH * Ee * Ee];
__device__ float g_ks[BH * Ee];

typedef unsigned long long u64;

__device__ __forceinline__ u64 pack2(float x, float y) {
    u64 r; asm("mov.b64 %0, {%1, %2};" : "=l"(r) : "f"(x), "f"(y)); return r;
}
__device__ __forceinline__ float2 unpack2(u64 v) {
    float2 r; asm("mov.b64 {%0, %1}, %2;" : "=f"(r.x), "=f"(r.y) : "l"(v)); return r;
}
__device__ __forceinline__ u64 ffma2(u64 a, u64 b, u64 c) {
    u64 d; asm("fma.rn.f32x2 %0, %1, %2, %3;" : "=l"(d) : "l"(a), "l"(b), "l"(c)); return d;
}
__device__ __forceinline__ u64 fmul2(u64 a, u64 b) {
    u64 d; asm("mul.rn.f32x2 %0, %1, %2;" : "=l"(d) : "l"(a), "l"(b)); return d;
}
__device__ __forceinline__ void cpa16(uint32_t dst, const float* src) {
    asm volatile("cp.async.cg.shared.global [%0], [%1], 16;" :: "r"(dst), "l"(src));
}
#define CP_COMMIT() asm volatile("cp.async.commit_group;")
#define CP_WAIT1()  asm volatile("cp.async.wait_group 1;")

// named producer/consumer barriers (id 0 reserved for __syncthreads)
#define BAR_SYNC(id)   asm volatile("bar.sync %0, 256;"   :: "r"(id) : "memory")
#define BAR_ARRIVE(id) asm volatile("bar.arrive %0, 256;" :: "r"(id) : "memory")
// consumer-only barrier (128 threads)
#define BAR_CONS()     asm volatile("bar.sync 5, 128;" ::: "memory")
#define FULLB(s)  (1 + (s))
#define EMPTYB(s) (3 + (s))

// Dup-pair row layout (stride 132 floats). Pair c = 8p+i at float
// 32*(i>>1) + 4p + 2*(i&1). Reader LDS.128 at 32j + 4g -> pairs (8g+2j, +1).

// ---------------------------------------------------------------------------
// Pass 1: KV_partial = phi(K)^T V per (head, L-split) + ksum_partial.
// Warps 0-3: softmax producers (LDG prefetched across the EMPTY wait).
// Warps 4-7: GEMM consumers (cp.async V ring, LDS, FFMA2). Full contraction.
// smem floats: v[2][4096]=8192 | phi[2][64*132]=16896 | kst[1024] = 26112
// ---------------------------------------------------------------------------
__global__ void __launch_bounds__(256, 2) k_pass1(const float* __restrict__ Kin,
                                                  const float* __restrict__ Vin,
                                                  const float* __restrict__ D1) {
    extern __shared__ __align__(16) float sm1[];
    float* s_v   = sm1;             // 2 x 4096
    float* s_phi = sm1 + 8192;      // 2 x 8448 (dup pairs, stride 132)
    float* s_kst = sm1 + 25088;     // 16 x 64
    const uint32_t sb = (uint32_t)__cvta_generic_to_shared(sm1);

    const int bh = blockIdx.x / SPLIT, sp = blockIdx.x % SPLIT;
    const int b = bh >> 4, h = bh & 15;
    const int tid = threadIdx.x, w = tid >> 5, lane = tid & 31;
    const float invT = 1.0f / log1pf(__expf(*D1));
    const float* Kb = Kin + (long)b * Ll * RS + h * Ee + (long)sp * ROWS1 * RS;
    const float* Vb = Vin + (long)b * Ll * RS + h * Ee + (long)sp * ROWS1 * RS;

    if (w < 4) {
        // ================= producers =================
        const int sub = lane >> 3, p = lane & 7;    // 8 lanes per row
        float ksl[8];
        #pragma unroll
        for (int i = 0; i < 8; i++) ksl[i] = 0.f;

        auto ldK = [&](int t, float4* A, float4* B) {
            const float* ksrc = Kb + (long)t * TILE * RS;
            #pragma unroll
            for (int it = 0; it < 4; it++) {
                const float* kp = ksrc + (long)(w * 16 + it * 4 + sub) * RS + 8 * p;
                A[it] = *(const float4*)kp;
                B[it] = *(const float4*)(kp + 4);
            }
        };
        auto compute = [&](int t, const float4* A, const float4* B) {
            float* phib = s_phi + (t & 1) * 8448;
            #pragma unroll
            for (int it = 0; it < 4; it++) {
                const int r = w * 16 + it * 4 + sub;
                float e0 = __expf((A[it].x < 0.f ? NEG_CLAMP : A[it].x) * invT);
                float e1 = __expf((A[it].y < 0.f ? NEG_CLAMP : A[it].y) * invT);
                float e2 = __expf((A[it].z < 0.f ? NEG_CLAMP : A[it].z) * invT);
                float e3 = __expf((A[it].w < 0.f ? NEG_CLAMP : A[it].w) * invT);
                float e4 = __expf((B[it].x < 0.f ? NEG_CLAMP : B[it].x) * invT);
                float e5 = __expf((B[it].y < 0.f ? NEG_CLAMP : B[it].y) * invT);
                float e6 = __expf((B[it].z < 0.f ? NEG_CLAMP : B[it].z) * invT);
                float e7 = __expf((B[it].w < 0.f ? NEG_CLAMP : B[it].w) * invT);
                float ls = ((e0 + e1) + (e2 + e3)) + ((e4 + e5) + (e6 + e7));
                ls += __shfl_xor_sync(0xffffffffu, ls, 1);
                ls += __shfl_xor_sync(0xffffffffu, ls, 2);
                ls += __shfl_xor_sync(0xffffffffu, ls, 4);
                float rs = 1.0f / ls;
                e0 *= rs; e1 *= rs; e2 *= rs; e3 *= rs;
                e4 *= rs; e5 *= rs; e6 *= rs; e7 *= rs;
                ksl[0] += e0; ksl[1] += e1; ksl[2] += e2; ksl[3] += e3;
                ksl[4] += e4; ksl[5] += e5; ksl[6] += e6; ksl[7] += e7;
                float* pr = phib + r * 132 + 4 * p;
                *(u64*)(pr)      = pack2(e0, e0);
                *(u64*)(pr + 2)  = pack2(e1, e1);
                *(u64*)(pr + 32) = pack2(e2, e2);
                *(u64*)(pr + 34) = pack2(e3, e3);
                *(u64*)(pr + 64) = pack2(e4, e4);
                *(u64*)(pr + 66) = pack2(e5, e5);
                *(u64*)(pr + 96) = pack2(e6, e6);
                *(u64*)(pr + 98) = pack2(e7, e7);
            }
        };
        auto prod_step = [&](int t, float4* curA, float4* curB,
                             float4* nxtA, float4* nxtB) {
            if (t + 1 < NT1) ldK(t + 1, nxtA, nxtB);  // LDG in flight during wait
            if (t >= 2) BAR_SYNC(EMPTYB(t & 1));
            compute(t, curA, curB);
            BAR_ARRIVE(FULLB(t & 1));
        };

        float4 A0[4], B0[4], A1[4], B1[4];
        ldK(0, A0, B0);
        for (int tt = 0; tt < NT1; tt += 2) {
            prod_step(tt,     A0, B0, A1, B1);
            prod_step(tt + 1, A1, B1, A0, B0);
        }
        // stage ksum partials
        float* kr = s_kst + (w * 4 + sub) * 64 + 8 * p;
        *(float4*)(kr)     = make_float4(ksl[0], ksl[1], ksl[2], ksl[3]);
        *(float4*)(kr + 4) = make_float4(ksl[4], ksl[5], ksl[6], ksl[7]);
    } else {
        // ================= consumers =================
        const int cw = tid & 127;
        const int eg = cw >> 4, dgi = cw & 15;   // e 8eg..+7, d 4dgi..+3
        u64 acc[8][2];
        #pragma unroll
        for (int i = 0; i < 8; i++) { acc[i][0] = 0ull; acc[i][1] = 0ull; }

        auto issue_copy = [&](int tile) {
            if (tile < NT1) {
                const float* vsrc = Vb + (long)tile * TILE * RS;
                const uint32_t vd = sb + (uint32_t)((tile & 1) * 4096) * 4u;
                #pragma unroll
                for (int c = 0; c < 8; c++) {
                    int lin = cw + 128 * c;
                    int r = lin >> 4, k = lin & 15;
                    cpa16(vd + (uint32_t)(r * 64 + k * 4) * 4u,
                          vsrc + (long)r * RS + k * 4);
                }
            }
            CP_COMMIT();
        };

        issue_copy(0);

        for (int t = 0; t < NT1; t++) {
            BAR_SYNC(FULLB(t & 1));   // phi(t) ready; all consumers past gemm(t-1)
            issue_copy(t + 1);        // slot (t+1)&1 free
            CP_WAIT1();               // OWN copies of v(t) landed
            BAR_CONS();               // ALL consumers' copies of v(t) landed
            const float* vt = s_v + (t & 1) * 4096;
            const float* pb = s_phi + (t & 1) * 8448;
            #pragma unroll 4
            for (int r = 0; r < TILE; r++) {
                const float* pr = pb + r * 132 + 4 * eg;
                ulonglong2 P0 = *(const ulonglong2*)(pr);
                ulonglong2 P1 = *(const ulonglong2*)(pr + 32);
                ulonglong2 P2 = *(const ulonglong2*)(pr + 64);
                ulonglong2 P3 = *(const ulonglong2*)(pr + 96);
                u64 pe[8] = {P0.x, P0.y, P1.x, P1.y, P2.x, P2.y, P3.x, P3.y};
                ulonglong2 V = *(const ulonglong2*)(vt + r * 64 + 4 * dgi);
                #pragma unroll
                for (int i = 0; i < 8; i++) {
                    acc[i][0] = ffma2(pe[i], V.x, acc[i][0]);
                    acc[i][1] = ffma2(pe[i], V.y, acc[i][1]);
                }
            }
            BAR_ARRIVE(EMPTYB(t & 1));
        }

        // full-contraction tile: write partial KV directly (no block reduction)
        float* dst = g_kv_part + ((long)sp * BH + bh) * 4096;
        #pragma unroll
        for (int i = 0; i < 8; i++) {
            float2 a = unpack2(acc[i][0]), c = unpack2(acc[i][1]);
            *(float4*)(dst + (8 * eg + i) * 64 + 4 * dgi) = make_float4(a.x, a.y, c.x, c.y);
        }
    }

    __syncthreads();
    if (tid < 64) {
        float s = 0.f;
        #pragma unroll
        for (int i = 0; i < 16; i++) s += s_kst[i * 64 + tid];
        g_ks_part[((long)sp * BH + bh) * 64 + tid] = s;
    }
}

// ---------------------------------------------------------------------------
// Deterministic split reduction (512 blocks)
// ---------------------------------------------------------------------------
__global__ void __launch_bounds__(256) k_reduce() {
    const int bh = blockIdx.x >> 2, part = blockIdx.x & 3;
    const int tid = threadIdx.x;
    const int i4 = part * 1024 + tid * 4;
    float4 s = make_float4(0.f, 0.f, 0.f, 0.f);
    #pragma unroll
    for (int sp = 0; sp < SPLIT; sp++) {
        float4 v = *(const float4*)(g_kv_part + ((long)sp * BH + bh) * 4096 + i4);
        s.x += v.x; s.y += v.y; s.z += v.z; s.w += v.w;
    }
    *(float4*)(g_kv + (long)bh * 4096 + i4) = s;
    if (part == 0 && tid < 64) {
        float t = 0.f;
        #pragma unroll
        for (int sp = 0; sp < SPLIT; sp++)
            t += g_ks_part[((long)sp * BH + bh) * 64 + tid];
        g_ks[(long)bh * 64 + tid] = t;
    }
}

// ---------------------------------------------------------------------------
// Pass 2: out_l = (phi(q_l) . KV) * z_l. 1024 blocks, one head x 512 rows.
// Warps 0-3 produce qT + z (LDG prefetched across waits); warps 4-7 GEMM+store.
// smem floats: kvd[64*128]=8192 | qT[2][64*130]=16640 | z[2][128] | ks[64]
// ---------------------------------------------------------------------------
__global__ void __launch_bounds__(256, 2) k_pass2(const float* __restrict__ Qin,
                                                  float* __restrict__ Out,
                                                  const float* __restrict__ D1) {
    extern __shared__ __align__(16) float sm2[];
    float* s_kvd = sm2;              // 8192 (dup pairs, stride 128)
    float* s_qT  = sm2 + 8192;       // 2 x 8320: [e][row], stride 130
    float* s_z   = sm2 + 24832;      // 2 x 128
    float* s_ks  = sm2 + 25088;      // 64

    const int bh = blockIdx.x >> 3, chunk = blockIdx.x & 7;
    const int b = bh >> 4, h = bh & 15;
    const int tid = threadIdx.x, w = tid >> 5, lane = tid & 31;
    const float invT = 1.0f / log1pf(__expf(*D1));
    const float* Qb = Qin + (long)b * Ll * RS + h * Ee + (long)chunk * CH2 * RS;
    float*       Ob = Out + (long)b * Ll * RS + h * Ee + (long)chunk * CH2 * RS;

    // stage KV duplicated + ksum (all threads), then diverge into roles
    {
        const float* kvsrc = g_kv + (long)bh * 4096;
        #pragma unroll
        for (int c = 0; c < 4; c++) {
            int i4 = tid + 256 * c;
            float4 v4 = *(const float4*)(kvsrc + i4 * 4);
            int e = i4 >> 4, d0 = (i4 & 15) * 4;
            float* rowb = s_kvd + e * 128 + 4 * (d0 >> 3);
            const int j2 = (d0 & 7) >> 1;   // 0 or 2
            *(u64*)(rowb + 32 * j2)           = pack2(v4.x, v4.x);
            *(u64*)(rowb + 32 * j2 + 2)       = pack2(v4.y, v4.y);
            *(u64*)(rowb + 32 * (j2 + 1))     = pack2(v4.z, v4.z);
            *(u64*)(rowb + 32 * (j2 + 1) + 2) = pack2(v4.w, v4.w);
        }
        if (tid < 64) s_ks[tid] = g_ks[(long)bh * 64 + tid];
    }
    __syncthreads();

    if (w < 4) {
        // ================= producers =================
        const int sub = lane >> 3, p = lane & 7;
        float myks[8];
        {
            float4 kA = *(const float4*)(s_ks + 8 * p);
            float4 kB = *(const float4*)(s_ks + 8 * p + 4);
            myks[0] = kA.x; myks[1] = kA.y; myks[2] = kA.z; myks[3] = kA.w;
            myks[4] = kB.x; myks[5] = kB.y; myks[6] = kB.z; myks[7] = kB.w;
        }
        auto ldQ = [&](int t, int half, float4* A, float4* B) {
            const float* qsrc = Qb + (long)t * T2 * RS;
            #pragma unroll
            for (int i2 = 0; i2 < 4; i2++) {
                const int r = w * 32 + (half * 4 + i2) * 4 + sub;
                const float* qp = qsrc + (long)r * RS + 8 * p;
                A[i2] = *(const float4*)qp;
                B[i2] = *(const float4*)(qp + 4);
            }
        };
        auto comp_half = [&](int t, int half, const float4* A, const float4* B) {
            float* qb = s_qT + (t & 1) * 8320;
            float* zb = s_z + (t & 1) * 128;
            #pragma unroll
            for (int i2 = 0; i2 < 4; i2++) {
                const int r = w * 32 + (half * 4 + i2) * 4 + sub;
                float e0 = __expf((A[i2].x < 0.f ? NEG_CLAMP : A[i2].x) * invT);
                float e1 = __expf((A[i2].y < 0.f ? NEG_CLAMP : A[i2].y) * invT);
                float e2 = __expf((A[i2].z < 0.f ? NEG_CLAMP : A[i2].z) * invT);
                float e3 = __expf((A[i2].w < 0.f ? NEG_CLAMP : A[i2].w) * invT);
                float e4 = __expf((B[i2].x < 0.f ? NEG_CLAMP : B[i2].x) * invT);
                float e5 = __expf((B[i2].y < 0.f ? NEG_CLAMP : B[i2].y) * invT);
                float e6 = __expf((B[i2].z < 0.f ? NEG_CLAMP : B[i2].z) * invT);
                float e7 = __expf((B[i2].w < 0.f ? NEG_CLAMP : B[i2].w) * invT);
                float ls = ((e0 + e1) + (e2 + e3)) + ((e4 + e5) + (e6 + e7));
                float dt = ((e0 * myks[0] + e1 * myks[1]) + (e2 * myks[2] + e3 * myks[3]))
                         + ((e4 * myks[4] + e5 * myks[5]) + (e6 * myks[6] + e7 * myks[7]));
                #pragma unroll
                for (int o = 1; o <= 4; o <<= 1) {
                    ls += __shfl_xor_sync(0xffffffffu, ls, o);
                    dt += __shfl_xor_sync(0xffffffffu, dt, o);
                }
                float rs = 1.0f / ls;
                float zz = 1.0f / (dt * rs + EPSV);
                e0 *= rs; e1 *= rs; e2 *= rs; e3 *= rs;
                e4 *= rs; e5 *= rs; e6 *= rs; e7 *= rs;
                qb[(8 * p + 0) * 130 + r] = e0;
                qb[(8 * p + 1) * 130 + r] = e1;
                qb[(8 * p + 2) * 130 + r] = e2;
                qb[(8 * p + 3) * 130 + r] = e3;
                qb[(8 * p + 4) * 130 + r] = e4;
                qb[(8 * p + 5) * 130 + r] = e5;
                qb[(8 * p + 6) * 130 + r] = e6;
                qb[(8 * p + 7) * 130 + r] = e7;
                if (p == 0) zb[r] = zz;
            }
        };

        float4 A0[4], B0[4], A1[4], B1[4];
        ldQ(0, 0, A0, B0);
        for (int t = 0; t < NT2; t++) {
            ldQ(t, 1, A1, B1);               // prefetch half1 before the wait
            if (t >= 2) BAR_SYNC(EMPTYB(t & 1));
            comp_half(t, 0, A0, B0);
            if (t + 1 < NT2) ldQ(t + 1, 0, A0, B0);  // prefetch next tile half0
            comp_half(t, 1, A1, B1);
            BAR_ARRIVE(FULLB(t & 1));
        }
    } else {
        // ================= consumers =================
        const int cw = tid & 127;
        const int rg = cw >> 3, dg = cw & 7;   // rows 8rg..+7, d 8dg..+7
        for (int t = 0; t < NT2; t++) {
            BAR_SYNC(FULLB(t & 1));
            const float* qb = s_qT + (t & 1) * 8320;
            const float* zb = s_z + (t & 1) * 128;
            u64 acc[4][8];
            #pragma unroll
            for (int pr = 0; pr < 4; pr++)
                #pragma unroll
                for (int j = 0; j < 8; j++) acc[pr][j] = 0ull;
            #pragma unroll 2
            for (int e = 0; e < Ee; e++) {
                const float* qc = qb + e * 130 + 8 * rg;
                u64 q0 = *(const u64*)(qc);
                u64 q1 = *(const u64*)(qc + 2);
                u64 q2 = *(const u64*)(qc + 4);
                u64 q3 = *(const u64*)(qc + 6);
                const float* kr = s_kvd + e * 128 + 4 * dg;
                ulonglong2 K0 = *(const ulonglong2*)(kr);
                ulonglong2 K1 = *(const ulonglong2*)(kr + 32);
                ulonglong2 K2 = *(const ulonglong2*)(kr + 64);
                ulonglong2 K3 = *(const ulonglong2*)(kr + 96);
                u64 kd[8] = {K0.x, K0.y, K1.x, K1.y, K2.x, K2.y, K3.x, K3.y};
                #pragma unroll
                for (int j = 0; j < 8; j++) {
                    acc[0][j] = ffma2(q0, kd[j], acc[0][j]);
                    acc[1][j] = ffma2(q1, kd[j], acc[1][j]);
                    acc[2][j] = ffma2(q2, kd[j], acc[2][j]);
                    acc[3][j] = ffma2(q3, kd[j], acc[3][j]);
                }
            }
            #pragma unroll
            for (int pr = 0; pr < 4; pr++) {
                const int r0 = 8 * rg + 2 * pr;
                const u64 zp = pack2(zb[r0], zb[r0 + 1]);
                float2 sc[8];
                #pragma unroll
                for (int j = 0; j < 8; j++) sc[j] = unpack2(fmul2(acc[pr][j], zp));
                float* oA = Ob + (long)(t * T2 + r0) * RS + 8 * dg;
                *(float4*)(oA)     = make_float4(sc[0].x, sc[1].x, sc[2].x, sc[3].x);
                *(float4*)(oA + 4) = make_float4(sc[4].x, sc[5].x, sc[6].x, sc[7].x);
                float* oB = oA + RS;
                *(float4*)(oB)     = make_float4(sc[0].y, sc[1].y, sc[2].y, sc[3].y);
                *(float4*)(oB + 4) = make_float4(sc[4].y, sc[5].y, sc[6].y, sc[7].y);
            }
            BAR_ARRIVE(EMPTYB(t & 1));
        }
    }
}

extern "C" void kernel_launch(void* const* d_in, const int* in_sizes, int n_in,
                              void* d_out, int out_size) {
    const float* Q  = (const float*)d_in[0];
    const float* K  = (const float*)d_in[1];
    const float* V  = (const float*)d_in[2];
    const float* D1 = (const float*)d_in[3];
    float* O = (float*)d_out;

    const int smem1 = 26112 * 4;  // 104448 B
    const int smem2 = 25152 * 4;  // 100608 B
    cudaFuncSetAttribute(k_pass1, cudaFuncAttributeMaxDynamicSharedMemorySize, smem1);
    cudaFuncSetAttribute(k_pass2, cudaFuncAttributeMaxDynamicSharedMemorySize, smem2);

    k_pass1 <<<BH * SPLIT, 256, smem1>>>(K, V, D1);
    k_reduce<<<BH * 4, 256>>>();
    k_pass2 <<<BH * 8, 256, smem2>>>(Q, O, D1);
}